// round 10
// baseline (speedup 1.0000x reference)
#include <cuda_runtime.h>
#include <cuda_fp16.h>
#include <cuda_bf16.h>
#include <math.h>

#define NNODES 50000
#define NEDGES 800000
#define HEADS  4
#define HD     128      // H*D
#define HD2    64       // HD/2 half2 per row
#define EMBW   384      // L*H*D
#define NCLS   32
#define NB     ((NNODES + 255) / 256)   // 196 scan blocks
#define XPAD2  260                      // duplicated X smem row stride (floats)
#define WPAD   68                      // padded W smem row stride (64 cols)
#define CHK    16                       // k-chunk
#define NCHK   8                        // 128 / CHK

typedef unsigned long long ull;

// packed f32x2 FMA: a = x*w + a (elementwise, exact fp32 semantics per lane)
#define FMA_F32X2(a, x, w) \
    asm("fma.rn.f32x2 %0, %1, %2, %0;" : "+l"(a) : "l"(x), "l"(w))

__device__ __forceinline__ void unpack2(ull v, float& lo, float& hi) {
    unsigned l, h;
    asm("mov.b64 {%0, %1}, %2;" : "=r"(l), "=r"(h) : "l"(v));
    lo = __uint_as_float(l); hi = __uint_as_float(h);
}
__device__ __forceinline__ ull pack2(float v) {
    ull r;
    asm("mov.b64 %0, {%1, %1};" : "=l"(r) : "f"(v));
    return r;
}

// ---------------- scratch (device globals; no allocation allowed) ----------
__device__ __half2 g_feath[NNODES * HD2];   // transformed features, fp16
__device__ float g_el[NNODES * HEADS];
__device__ float g_er[NNODES * HEADS];
__device__ float g_emb[NNODES * EMBW];
__device__ int g_deg[NNODES];
__device__ int g_off[NNODES];
__device__ int g_cursor[NNODES];
__device__ int g_bsum[NB];
__device__ int g_csrc[NEDGES];              // src node ids, grouped by dst

// ---------------- CSR build kernels -----------------------------------------

__global__ void zero_deg_kernel(int* deg) {
    int i = blockIdx.x * blockDim.x + threadIdx.x;
    if (i < NNODES) deg[i] = 0;
}

__global__ void hist_kernel(const int* __restrict__ dst, int* __restrict__ deg) {
    int e = blockIdx.x * blockDim.x + threadIdx.x;
    if (e < NEDGES) atomicAdd(&deg[dst[e]], 1);
}

__global__ void scan_block_kernel(const int* __restrict__ deg,
                                  int* __restrict__ off, int* __restrict__ bsum) {
    __shared__ int sh[256];
    int i = blockIdx.x * 256 + threadIdx.x;
    int v = (i < NNODES) ? deg[i] : 0;
    sh[threadIdx.x] = v;
    __syncthreads();
    for (int o = 1; o < 256; o <<= 1) {
        int t = (threadIdx.x >= o) ? sh[threadIdx.x - o] : 0;
        __syncthreads();
        sh[threadIdx.x] += t;
        __syncthreads();
    }
    if (i < NNODES) off[i] = sh[threadIdx.x] - v;   // exclusive
    if (threadIdx.x == 255) bsum[blockIdx.x] = sh[255];
}

__global__ void scan_bsum_kernel(int* __restrict__ bsum) {
    __shared__ int sh[256];
    int v = (threadIdx.x < NB) ? bsum[threadIdx.x] : 0;
    sh[threadIdx.x] = v;
    __syncthreads();
    for (int o = 1; o < 256; o <<= 1) {
        int t = (threadIdx.x >= o) ? sh[threadIdx.x - o] : 0;
        __syncthreads();
        sh[threadIdx.x] += t;
        __syncthreads();
    }
    if (threadIdx.x < NB) bsum[threadIdx.x] = sh[threadIdx.x] - v;
}

__global__ void add_off_kernel(int* __restrict__ off, const int* __restrict__ bsum,
                               int* __restrict__ cursor) {
    int i = blockIdx.x * 256 + threadIdx.x;
    if (i < NNODES) {
        int o = off[i] + bsum[blockIdx.x];
        off[i] = o;
        cursor[i] = o;
    }
}

__global__ void scatter_kernel(const int* __restrict__ dst, const int* __restrict__ src,
                               int* __restrict__ cursor, int* __restrict__ csrc) {
    int e = blockIdx.x * blockDim.x + threadIdx.x;
    if (e < NEDGES) {
        int p = atomicAdd(&cursor[dst[e]], 1);
        csrc[p] = src[e];
    }
}

// ---------------- compute kernels -------------------------------------------

// feat[N,128] = in[N,128] @ W[128,128] (stored fp16), fused el/er epilogue.
// Grid: (row blocks)*2; block = 128 rows x 64 cols. 256 threads, thread tile
// 8x4 computed as f32x2 pairs, double-buffered 16-k chunks, 2 CTAs/SM.
// X smem duplicated {v,v} so one LDS.128 feeds two row-broadcast FMA2 pairs.
__global__ __launch_bounds__(256, 2) void gemm128_kernel(
    const float* __restrict__ in, int in_stride,
    const float* __restrict__ W,
    const float* __restrict__ al, const float* __restrict__ ar,
    __half2* __restrict__ feath,
    float* __restrict__ el, float* __restrict__ er,
    int nrows)
{
    __shared__ float Xs2[2][CHK * XPAD2];  // 2 x 16.6 KB, duplicated pairs
    __shared__ float Ws[2][CHK * WPAD];    // 2 x 4.35 KB

    const int t       = threadIdx.x;
    const int ct      = t & 15;
    const int rt      = t >> 4;
    const int rb      = blockIdx.x >> 1;
    const int colbase = (blockIdx.x & 1) * 64;
    const int row0    = rb * 128;

    const int lk = t & 15;    // loader: k within chunk
    const int lr = t >> 4;    // loader: base element

    ull acc01[8], acc23[8];
#pragma unroll
    for (int r = 0; r < 8; r++) { acc01[r] = 0ull; acc23[r] = 0ull; }
    float px[8], pw[4];

    // chunk 0 straight to smem
#pragma unroll
    for (int a = 0; a < 8; a++) {
        int r  = lr + a * 16;
        int gr = row0 + r;
        float v = (gr < nrows) ? in[gr * in_stride + lk] : 0.0f;
        *(float2*)&Xs2[0][lk * XPAD2 + r * 2] = make_float2(v, v);
    }
#pragma unroll
    for (int a = 0; a < 4; a++) {
        int c = lr + a * 16;
        Ws[0][lk * WPAD + c] = W[lk * 128 + colbase + c];
    }
    __syncthreads();

    for (int c = 0; c < NCHK; c++) {
        const int cur = c & 1;
        if (c + 1 < NCHK) {
            const int kb = (c + 1) * CHK;
#pragma unroll
            for (int a = 0; a < 8; a++) {
                int r  = lr + a * 16;
                int gr = row0 + r;
                px[a] = (gr < nrows) ? in[gr * in_stride + kb + lk] : 0.0f;
            }
#pragma unroll
            for (int a = 0; a < 4; a++) {
                int cc = lr + a * 16;
                pw[a] = W[(kb + lk) * 128 + colbase + cc];
            }
        }
#pragma unroll
        for (int k = 0; k < CHK; k++) {
            const float* xb = &Xs2[cur][k * XPAD2 + rt * 16];
            ulonglong2 xp0 = *(const ulonglong2*)(xb);       // rows 0,1
            ulonglong2 xp1 = *(const ulonglong2*)(xb + 4);   // rows 2,3
            ulonglong2 xp2 = *(const ulonglong2*)(xb + 8);   // rows 4,5
            ulonglong2 xp3 = *(const ulonglong2*)(xb + 12);  // rows 6,7
            ulonglong2 wv  = *(const ulonglong2*)&Ws[cur][k * WPAD + ct * 4];
            ull xr[8] = { xp0.x, xp0.y, xp1.x, xp1.y, xp2.x, xp2.y, xp3.x, xp3.y };
#pragma unroll
            for (int r = 0; r < 8; r++) {
                FMA_F32X2(acc01[r], xr[r], wv.x);
                FMA_F32X2(acc23[r], xr[r], wv.y);
            }
        }
        if (c + 1 < NCHK) {
            const int nxt = cur ^ 1;
#pragma unroll
            for (int a = 0; a < 8; a++) {
                int r = lr + a * 16;
                *(float2*)&Xs2[nxt][lk * XPAD2 + r * 2] = make_float2(px[a], px[a]);
            }
#pragma unroll
            for (int a = 0; a < 4; a++) {
                int cc = lr + a * 16;
                Ws[nxt][lk * WPAD + cc] = pw[a];
            }
            __syncthreads();
        }
    }

    // epilogue: attention coefficients (fp32) + fp16 feat store
    const int head = (colbase + ct * 4) >> 5;
    float4 alv = *(const float4*)&al[colbase + ct * 4];
    float4 arv = *(const float4*)&ar[colbase + ct * 4];

#pragma unroll
    for (int r = 0; r < 8; r++) {
        float c0, c1, c2, c3;
        unpack2(acc01[r], c0, c1);
        unpack2(acc23[r], c2, c3);
        int gr = row0 + rt * 8 + r;
        float vl = c0 * alv.x + c1 * alv.y + c2 * alv.z + c3 * alv.w;
        float vr = c0 * arv.x + c1 * arv.y + c2 * arv.z + c3 * arv.w;
        vl += __shfl_xor_sync(0xFFFFFFFFu, vl, 1);
        vr += __shfl_xor_sync(0xFFFFFFFFu, vr, 1);
        vl += __shfl_xor_sync(0xFFFFFFFFu, vl, 2);
        vr += __shfl_xor_sync(0xFFFFFFFFu, vr, 2);
        vl += __shfl_xor_sync(0xFFFFFFFFu, vl, 4);
        vr += __shfl_xor_sync(0xFFFFFFFFu, vr, 4);
        if (gr < nrows) {
            __half2 h01 = __floats2half2_rn(c0, c1);
            __half2 h23 = __floats2half2_rn(c2, c3);
            *(uint2*)&feath[gr * HD2 + (colbase >> 1) + ct * 2] =
                make_uint2(*(unsigned*)&h01, *(unsigned*)&h23);
            if ((ct & 7) == 0) {
                el[gr * HEADS + head] = vl;
                er[gr * HEADS + head] = vr;
            }
        }
    }
}

// Fused per-destination softmax + aggregation + ELU + store. Warp per node.
// Lane owns features [lane*4, lane*4+4) (2 half2); head = lane>>3. Unroll x4.
__global__ __launch_bounds__(256) void gat_aggregate_kernel(
    const __half2* __restrict__ feath,
    const float* __restrict__ el, const float* __restrict__ er,
    const int* __restrict__ off, const int* __restrict__ deg,
    const int* __restrict__ csrc,
    float* __restrict__ emb, int col0)
{
    int warp = (blockIdx.x * blockDim.x + threadIdx.x) >> 5;
    if (warp >= NNODES) return;
    const int lane = threadIdx.x & 31;
    const int n    = warp;
    const int base = off[n];
    const int dg   = deg[n];

    const int h    = lane >> 3;
    const int f2   = lane * 2;          // half2 column index
    const float erh = er[n * 4 + h];

    float a0 = 0.f, a1 = 0.f, a2 = 0.f, a3 = 0.f, ssum = 0.f;
    int i = 0;
    for (; i + 4 <= dg; i += 4) {
        int s0 = csrc[base + i + 0];
        int s1 = csrc[base + i + 1];
        int s2 = csrc[base + i + 2];
        int s3 = csrc[base + i + 3];
        float x0 = el[s0 * 4 + h], x1 = el[s1 * 4 + h];
        float x2 = el[s2 * 4 + h], x3 = el[s3 * 4 + h];
        uint2 u0 = *(const uint2*)&feath[s0 * HD2 + f2];
        uint2 u1 = *(const uint2*)&feath[s1 * HD2 + f2];
        uint2 u2 = *(const uint2*)&feath[s2 * HD2 + f2];
        uint2 u3 = *(const uint2*)&feath[s3 * HD2 + f2];
        x0 += erh; x0 = (x0 > 0.f) ? x0 : 0.2f * x0; float e0 = __expf(x0);
        x1 += erh; x1 = (x1 > 0.f) ? x1 : 0.2f * x1; float e1 = __expf(x1);
        x2 += erh; x2 = (x2 > 0.f) ? x2 : 0.2f * x2; float e2 = __expf(x2);
        x3 += erh; x3 = (x3 > 0.f) ? x3 : 0.2f * x3; float e3 = __expf(x3);
        ssum += (e0 + e1) + (e2 + e3);
        float2 fa, fb;
        fa = __half22float2(*(__half2*)&u0.x); fb = __half22float2(*(__half2*)&u0.y);
        a0 = fmaf(e0, fa.x, a0); a1 = fmaf(e0, fa.y, a1);
        a2 = fmaf(e0, fb.x, a2); a3 = fmaf(e0, fb.y, a3);
        fa = __half22float2(*(__half2*)&u1.x); fb = __half22float2(*(__half2*)&u1.y);
        a0 = fmaf(e1, fa.x, a0); a1 = fmaf(e1, fa.y, a1);
        a2 = fmaf(e1, fb.x, a2); a3 = fmaf(e1, fb.y, a3);
        fa = __half22float2(*(__half2*)&u2.x); fb = __half22float2(*(__half2*)&u2.y);
        a0 = fmaf(e2, fa.x, a0); a1 = fmaf(e2, fa.y, a1);
        a2 = fmaf(e2, fb.x, a2); a3 = fmaf(e2, fb.y, a3);
        fa = __half22float2(*(__half2*)&u3.x); fb = __half22float2(*(__half2*)&u3.y);
        a0 = fmaf(e3, fa.x, a0); a1 = fmaf(e3, fa.y, a1);
        a2 = fmaf(e3, fb.x, a2); a3 = fmaf(e3, fb.y, a3);
    }
    for (; i < dg; i++) {
        int s = csrc[base + i];
        float x = el[s * 4 + h] + erh;
        x = (x > 0.f) ? x : 0.2f * x;
        float ex = __expf(x);
        ssum += ex;
        uint2 u = *(const uint2*)&feath[s * HD2 + f2];
        float2 fa = __half22float2(*(__half2*)&u.x);
        float2 fb = __half22float2(*(__half2*)&u.y);
        a0 = fmaf(ex, fa.x, a0); a1 = fmaf(ex, fa.y, a1);
        a2 = fmaf(ex, fb.x, a2); a3 = fmaf(ex, fb.y, a3);
    }
    float inv = (ssum != 0.f) ? (1.0f / ssum) : 0.0f;
    a0 *= inv; a1 *= inv; a2 *= inv; a3 *= inv;
    a0 = (a0 > 0.f) ? a0 : expm1f(a0);
    a1 = (a1 > 0.f) ? a1 : expm1f(a1);
    a2 = (a2 > 0.f) ? a2 : expm1f(a2);
    a3 = (a3 > 0.f) ? a3 : expm1f(a3);
    *(float4*)&emb[n * EMBW + col0 + lane * 4] = make_float4(a0, a1, a2, a3);
}

// logits = emb @ Wproj via f32x2. Block: 32 nodes x 32 classes.
// thread t = (nl:16, cp:16): nodes nb+nl, nb+nl+16; classes 2cp, 2cp+1.
__global__ __launch_bounds__(256) void proj_kernel(
    const float* __restrict__ emb,
    const float* __restrict__ Wp,
    float* __restrict__ out)
{
    __shared__ float Ws[EMBW * NCLS];   // 48 KB, k-major (class pairs contiguous)
    int t = threadIdx.x;
    for (int i = t; i < EMBW * NCLS; i += 256) Ws[i] = Wp[i];
    __syncthreads();

    const int cp = t & 15;
    const int nl = t >> 4;
    const int nb = blockIdx.x * 32;
    int nA = nb + nl;
    int nB = nb + nl + 16;
    int mA = min(nA, NNODES - 1), mB = min(nB, NNODES - 1);

    ull accA = 0ull, accB = 0ull;
#pragma unroll 4
    for (int k = 0; k < EMBW; k += 4) {
        float4 xA = __ldg((const float4*)&emb[mA * EMBW + k]);
        float4 xB = __ldg((const float4*)&emb[mB * EMBW + k]);
        ull w0 = *(const ull*)&Ws[(k + 0) * NCLS + cp * 2];
        ull w1 = *(const ull*)&Ws[(k + 1) * NCLS + cp * 2];
        ull w2 = *(const ull*)&Ws[(k + 2) * NCLS + cp * 2];
        ull w3 = *(const ull*)&Ws[(k + 3) * NCLS + cp * 2];
        FMA_F32X2(accA, pack2(xA.x), w0);
        FMA_F32X2(accA, pack2(xA.y), w1);
        FMA_F32X2(accA, pack2(xA.z), w2);
        FMA_F32X2(accA, pack2(xA.w), w3);
        FMA_F32X2(accB, pack2(xB.x), w0);
        FMA_F32X2(accB, pack2(xB.y), w1);
        FMA_F32X2(accB, pack2(xB.z), w2);
        FMA_F32X2(accB, pack2(xB.w), w3);
    }
    if (nA < NNODES) *(ull*)&out[nA * NCLS + cp * 2] = accA;
    if (nB < NNODES) *(ull*)&out[nB * NCLS + cp * 2] = accB;
}

// ---------------- host launch ----------------------------------------------
extern "C" void kernel_launch(void* const* d_in, const int* in_sizes, int n_in,
                              void* d_out, int out_size)
{
    const float* x    = (const float*)d_in[0];
    const int*   src  = (const int*)  d_in[1];
    const int*   dst  = (const int*)  d_in[2];
    const float* W[3]  = { (const float*)d_in[3], (const float*)d_in[6], (const float*)d_in[9]  };
    const float* al[3] = { (const float*)d_in[4], (const float*)d_in[7], (const float*)d_in[10] };
    const float* ar[3] = { (const float*)d_in[5], (const float*)d_in[8], (const float*)d_in[11] };
    const float* Wproj = (const float*)d_in[12];
    float* out = (float*)d_out;

    float *el, *er, *emb;
    __half2* feath;
    int *deg, *off, *cursor, *bsum, *csrc;
    cudaGetSymbolAddress((void**)&feath,  g_feath);
    cudaGetSymbolAddress((void**)&el,     g_el);
    cudaGetSymbolAddress((void**)&er,     g_er);
    cudaGetSymbolAddress((void**)&emb,    g_emb);
    cudaGetSymbolAddress((void**)&deg,    g_deg);
    cudaGetSymbolAddress((void**)&off,    g_off);
    cudaGetSymbolAddress((void**)&cursor, g_cursor);
    cudaGetSymbolAddress((void**)&bsum,   g_bsum);
    cudaGetSymbolAddress((void**)&csrc,   g_csrc);

    const int edge_blocks = (NEDGES + 255) / 256;
    const int gemm_blocks = ((NNODES + 127) / 128) * 2;   // 2 col-blocks per row-block
    const int aggr_blocks = (NNODES * 32 + 255) / 256;

    // CSR build interleaved with layer-0 GEMM (GEMM is CSR-independent);
    // GEMM sits at launch position 4 so the profiler samples it.
    zero_deg_kernel<<<NB, 256>>>(deg);
    hist_kernel<<<edge_blocks, 256>>>(dst, deg);
    scan_block_kernel<<<NB, 256>>>(deg, off, bsum);
    gemm128_kernel<<<gemm_blocks, 256>>>(x, 128, W[0], al[0], ar[0],
                                         feath, el, er, NNODES);
    scan_bsum_kernel<<<1, 256>>>(bsum);
    add_off_kernel<<<NB, 256>>>(off, bsum, cursor);
    scatter_kernel<<<edge_blocks, 256>>>(dst, src, cursor, csrc);

    gat_aggregate_kernel<<<aggr_blocks, 256>>>(feath, el, er,
                                               off, deg, csrc, emb, 0);
    for (int l = 1; l < 3; l++) {
        gemm128_kernel<<<gemm_blocks, 256>>>(emb + (l - 1) * HD, EMBW, W[l],
                                             al[l], ar[l], feath, el, er, NNODES);
        gat_aggregate_kernel<<<aggr_blocks, 256>>>(feath, el, er,
                                                   off, deg, csrc, emb, l * HD);
    }

    proj_kernel<<<(NNODES + 31) / 32, 256>>>(emb, Wproj, out);
}

// round 11
// speedup vs baseline: 1.0887x; 1.0887x over previous
#include <cuda_runtime.h>
#include <cuda_fp16.h>
#include <cuda_bf16.h>
#include <math.h>

#define NNODES 50000
#define NEDGES 800000
#define HEADS  4
#define HD     128      // H*D
#define HD2    64       // HD/2 half2 per row
#define EMBW   384      // L*H*D
#define NCLS   32
#define NB     ((NNODES + 255) / 256)   // 196 scan blocks
#define XPAD   132                      // padded X smem row stride (128 rows)
#define WPAD   68                       // padded W smem row stride (64 cols)
#define CHK    16                       // k-chunk
#define NCHK   8                        // 128 / CHK

typedef unsigned long long ull;

// packed f32x2 FMA: a = x*w + a (elementwise, exact fp32 semantics per lane)
#define FMA_F32X2(a, x, w) \
    asm("fma.rn.f32x2 %0, %1, %2, %0;" : "+l"(a) : "l"(x), "l"(w))

__device__ __forceinline__ ull pack2(float v) {
    ull r;
    asm("mov.b64 %0, {%1, %1};" : "=l"(r) : "f"(v));
    return r;
}

// ---------------- scratch (device globals; no allocation allowed) ----------
__device__ __half2 g_feath[NNODES * HD2];   // transformed features, fp16
__device__ float g_el[NNODES * HEADS];
__device__ float g_er[NNODES * HEADS];
__device__ float g_emb[NNODES * EMBW];
__device__ int g_deg[NNODES];
__device__ int g_off[NNODES];
__device__ int g_cursor[NNODES];
__device__ int g_bsum[NB];
__device__ int g_csrc[NEDGES];              // src node ids, grouped by dst

// ---------------- CSR build kernels -----------------------------------------

__global__ void zero_deg_kernel(int* deg) {
    int i = blockIdx.x * blockDim.x + threadIdx.x;
    if (i < NNODES) deg[i] = 0;
}

__global__ void hist_kernel(const int* __restrict__ dst, int* __restrict__ deg) {
    int e = blockIdx.x * blockDim.x + threadIdx.x;
    if (e < NEDGES) atomicAdd(&deg[dst[e]], 1);
}

__global__ void scan_block_kernel(const int* __restrict__ deg,
                                  int* __restrict__ off, int* __restrict__ bsum) {
    __shared__ int sh[256];
    int i = blockIdx.x * 256 + threadIdx.x;
    int v = (i < NNODES) ? deg[i] : 0;
    sh[threadIdx.x] = v;
    __syncthreads();
    for (int o = 1; o < 256; o <<= 1) {
        int t = (threadIdx.x >= o) ? sh[threadIdx.x - o] : 0;
        __syncthreads();
        sh[threadIdx.x] += t;
        __syncthreads();
    }
    if (i < NNODES) off[i] = sh[threadIdx.x] - v;   // exclusive
    if (threadIdx.x == 255) bsum[blockIdx.x] = sh[255];
}

__global__ void scan_bsum_kernel(int* __restrict__ bsum) {
    __shared__ int sh[256];
    int v = (threadIdx.x < NB) ? bsum[threadIdx.x] : 0;
    sh[threadIdx.x] = v;
    __syncthreads();
    for (int o = 1; o < 256; o <<= 1) {
        int t = (threadIdx.x >= o) ? sh[threadIdx.x - o] : 0;
        __syncthreads();
        sh[threadIdx.x] += t;
        __syncthreads();
    }
    if (threadIdx.x < NB) bsum[threadIdx.x] = sh[threadIdx.x] - v;
}

__global__ void add_off_kernel(int* __restrict__ off, const int* __restrict__ bsum,
                               int* __restrict__ cursor) {
    int i = blockIdx.x * 256 + threadIdx.x;
    if (i < NNODES) {
        int o = off[i] + bsum[blockIdx.x];
        off[i] = o;
        cursor[i] = o;
    }
}

__global__ void scatter_kernel(const int* __restrict__ dst, const int* __restrict__ src,
                               int* __restrict__ cursor, int* __restrict__ csrc) {
    int e = blockIdx.x * blockDim.x + threadIdx.x;
    if (e < NEDGES) {
        int p = atomicAdd(&cursor[dst[e]], 1);
        csrc[p] = src[e];
    }
}

// ---------------- compute kernels -------------------------------------------

// feat[N,128] = in[N,128] @ W[128,128] (stored fp16), fused el/er epilogue.
// Round-8 proven structure: grid (rowblocks)*2, block = 128 rows x 64 cols,
// 256 threads, thread tile 8x4 scalar FFMA, double-buffered k=16, 2 CTAs/SM.
__global__ __launch_bounds__(256, 2) void gemm128_kernel(
    const float* __restrict__ in, int in_stride,
    const float* __restrict__ W,
    const float* __restrict__ al, const float* __restrict__ ar,
    __half2* __restrict__ feath,
    float* __restrict__ el, float* __restrict__ er,
    int nrows)
{
    __shared__ float Xs[2][CHK * XPAD];   // 2 x 8.45 KB (k-major: Xs[k][row])
    __shared__ float Ws[2][CHK * WPAD];   // 2 x 4.35 KB (Ws[k][col-colbase])

    const int t       = threadIdx.x;
    const int ct      = t & 15;
    const int rt      = t >> 4;
    const int rb      = blockIdx.x >> 1;
    const int colbase = (blockIdx.x & 1) * 64;
    const int row0    = rb * 128;

    const int lk = t & 15;    // loader: k within chunk
    const int lr = t >> 4;    // loader: base element

    float acc[8][4] = {};
    float px[8], pw[4];

    // chunk 0 straight to smem
#pragma unroll
    for (int a = 0; a < 8; a++) {
        int r  = lr + a * 16;
        int gr = row0 + r;
        Xs[0][lk * XPAD + r] = (gr < nrows) ? in[gr * in_stride + lk] : 0.0f;
    }
#pragma unroll
    for (int a = 0; a < 4; a++) {
        int c = lr + a * 16;
        Ws[0][lk * WPAD + c] = W[lk * 128 + colbase + c];
    }
    __syncthreads();

    for (int c = 0; c < NCHK; c++) {
        const int cur = c & 1;
        if (c + 1 < NCHK) {
            const int kb = (c + 1) * CHK;
#pragma unroll
            for (int a = 0; a < 8; a++) {
                int r  = lr + a * 16;
                int gr = row0 + r;
                px[a] = (gr < nrows) ? in[gr * in_stride + kb + lk] : 0.0f;
            }
#pragma unroll
            for (int a = 0; a < 4; a++) {
                int cc = lr + a * 16;
                pw[a] = W[(kb + lk) * 128 + colbase + cc];
            }
        }
#pragma unroll
        for (int k = 0; k < CHK; k++) {
            float4 x0 = *(const float4*)&Xs[cur][k * XPAD + rt * 8];
            float4 x1 = *(const float4*)&Xs[cur][k * XPAD + rt * 8 + 4];
            float4 w  = *(const float4*)&Ws[cur][k * WPAD + ct * 4];
            float xr[8] = { x0.x, x0.y, x0.z, x0.w, x1.x, x1.y, x1.z, x1.w };
#pragma unroll
            for (int r = 0; r < 8; r++) {
                acc[r][0] = fmaf(xr[r], w.x, acc[r][0]);
                acc[r][1] = fmaf(xr[r], w.y, acc[r][1]);
                acc[r][2] = fmaf(xr[r], w.z, acc[r][2]);
                acc[r][3] = fmaf(xr[r], w.w, acc[r][3]);
            }
        }
        if (c + 1 < NCHK) {
            const int nxt = cur ^ 1;
#pragma unroll
            for (int a = 0; a < 8; a++) {
                int r = lr + a * 16;
                Xs[nxt][lk * XPAD + r] = px[a];
            }
#pragma unroll
            for (int a = 0; a < 4; a++) {
                int cc = lr + a * 16;
                Ws[nxt][lk * WPAD + cc] = pw[a];
            }
            __syncthreads();
        }
    }

    // epilogue: attention coefficients (fp32) + fp16 feat store
    const int head = (colbase + ct * 4) >> 5;
    float4 alv = *(const float4*)&al[colbase + ct * 4];
    float4 arv = *(const float4*)&ar[colbase + ct * 4];

#pragma unroll
    for (int r = 0; r < 8; r++) {
        int gr = row0 + rt * 8 + r;
        float vl = acc[r][0] * alv.x + acc[r][1] * alv.y +
                   acc[r][2] * alv.z + acc[r][3] * alv.w;
        float vr = acc[r][0] * arv.x + acc[r][1] * arv.y +
                   acc[r][2] * arv.z + acc[r][3] * arv.w;
        vl += __shfl_xor_sync(0xFFFFFFFFu, vl, 1);
        vr += __shfl_xor_sync(0xFFFFFFFFu, vr, 1);
        vl += __shfl_xor_sync(0xFFFFFFFFu, vl, 2);
        vr += __shfl_xor_sync(0xFFFFFFFFu, vr, 2);
        vl += __shfl_xor_sync(0xFFFFFFFFu, vl, 4);
        vr += __shfl_xor_sync(0xFFFFFFFFu, vr, 4);
        if (gr < nrows) {
            __half2 h01 = __floats2half2_rn(acc[r][0], acc[r][1]);
            __half2 h23 = __floats2half2_rn(acc[r][2], acc[r][3]);
            *(uint2*)&feath[gr * HD2 + (colbase >> 1) + ct * 2] =
                make_uint2(*(unsigned*)&h01, *(unsigned*)&h23);
            if ((ct & 7) == 0) {
                el[gr * HEADS + head] = vl;
                er[gr * HEADS + head] = vr;
            }
        }
    }
}

// Fused per-destination softmax + aggregation + ELU + store. Warp per node.
// Lane owns features [lane*4, lane*4+4) (2 half2); head = lane>>3. Unroll x4.
__global__ __launch_bounds__(256) void gat_aggregate_kernel(
    const __half2* __restrict__ feath,
    const float* __restrict__ el, const float* __restrict__ er,
    const int* __restrict__ off, const int* __restrict__ deg,
    const int* __restrict__ csrc,
    float* __restrict__ emb, int col0)
{
    int warp = (blockIdx.x * blockDim.x + threadIdx.x) >> 5;
    if (warp >= NNODES) return;
    const int lane = threadIdx.x & 31;
    const int n    = warp;
    const int base = off[n];
    const int dg   = deg[n];

    const int h    = lane >> 3;
    const int f2   = lane * 2;          // half2 column index
    const float erh = er[n * 4 + h];

    float a0 = 0.f, a1 = 0.f, a2 = 0.f, a3 = 0.f, ssum = 0.f;
    int i = 0;
    for (; i + 4 <= dg; i += 4) {
        int s0 = csrc[base + i + 0];
        int s1 = csrc[base + i + 1];
        int s2 = csrc[base + i + 2];
        int s3 = csrc[base + i + 3];
        float x0 = el[s0 * 4 + h], x1 = el[s1 * 4 + h];
        float x2 = el[s2 * 4 + h], x3 = el[s3 * 4 + h];
        uint2 u0 = *(const uint2*)&feath[s0 * HD2 + f2];
        uint2 u1 = *(const uint2*)&feath[s1 * HD2 + f2];
        uint2 u2 = *(const uint2*)&feath[s2 * HD2 + f2];
        uint2 u3 = *(const uint2*)&feath[s3 * HD2 + f2];
        x0 += erh; x0 = (x0 > 0.f) ? x0 : 0.2f * x0; float e0 = __expf(x0);
        x1 += erh; x1 = (x1 > 0.f) ? x1 : 0.2f * x1; float e1 = __expf(x1);
        x2 += erh; x2 = (x2 > 0.f) ? x2 : 0.2f * x2; float e2 = __expf(x2);
        x3 += erh; x3 = (x3 > 0.f) ? x3 : 0.2f * x3; float e3 = __expf(x3);
        ssum += (e0 + e1) + (e2 + e3);
        float2 fa, fb;
        fa = __half22float2(*(__half2*)&u0.x); fb = __half22float2(*(__half2*)&u0.y);
        a0 = fmaf(e0, fa.x, a0); a1 = fmaf(e0, fa.y, a1);
        a2 = fmaf(e0, fb.x, a2); a3 = fmaf(e0, fb.y, a3);
        fa = __half22float2(*(__half2*)&u1.x); fb = __half22float2(*(__half2*)&u1.y);
        a0 = fmaf(e1, fa.x, a0); a1 = fmaf(e1, fa.y, a1);
        a2 = fmaf(e1, fb.x, a2); a3 = fmaf(e1, fb.y, a3);
        fa = __half22float2(*(__half2*)&u2.x); fb = __half22float2(*(__half2*)&u2.y);
        a0 = fmaf(e2, fa.x, a0); a1 = fmaf(e2, fa.y, a1);
        a2 = fmaf(e2, fb.x, a2); a3 = fmaf(e2, fb.y, a3);
        fa = __half22float2(*(__half2*)&u3.x); fb = __half22float2(*(__half2*)&u3.y);
        a0 = fmaf(e3, fa.x, a0); a1 = fmaf(e3, fa.y, a1);
        a2 = fmaf(e3, fb.x, a2); a3 = fmaf(e3, fb.y, a3);
    }
    for (; i < dg; i++) {
        int s = csrc[base + i];
        float x = el[s * 4 + h] + erh;
        x = (x > 0.f) ? x : 0.2f * x;
        float ex = __expf(x);
        ssum += ex;
        uint2 u = *(const uint2*)&feath[s * HD2 + f2];
        float2 fa = __half22float2(*(__half2*)&u.x);
        float2 fb = __half22float2(*(__half2*)&u.y);
        a0 = fmaf(ex, fa.x, a0); a1 = fmaf(ex, fa.y, a1);
        a2 = fmaf(ex, fb.x, a2); a3 = fmaf(ex, fb.y, a3);
    }
    float inv = (ssum != 0.f) ? (1.0f / ssum) : 0.0f;
    a0 *= inv; a1 *= inv; a2 *= inv; a3 *= inv;
    a0 = (a0 > 0.f) ? a0 : expm1f(a0);
    a1 = (a1 > 0.f) ? a1 : expm1f(a1);
    a2 = (a2 > 0.f) ? a2 : expm1f(a2);
    a3 = (a3 > 0.f) ? a3 : expm1f(a3);
    *(float4*)&emb[n * EMBW + col0 + lane * 4] = make_float4(a0, a1, a2, a3);
}

// logits = emb @ Wproj via f32x2. Block: 32 nodes x 32 classes.
// thread t = (nl:16, cp:16): nodes nb+nl, nb+nl+16; classes 2cp, 2cp+1.
__global__ __launch_bounds__(256) void proj_kernel(
    const float* __restrict__ emb,
    const float* __restrict__ Wp,
    float* __restrict__ out)
{
    __shared__ float Ws[EMBW * NCLS];   // 48 KB, k-major (class pairs contiguous)
    int t = threadIdx.x;
    for (int i = t; i < EMBW * NCLS; i += 256) Ws[i] = Wp[i];
    __syncthreads();

    const int cp = t & 15;
    const int nl = t >> 4;
    const int nb = blockIdx.x * 32;
    int nA = nb + nl;
    int nB = nb + nl + 16;
    int mA = min(nA, NNODES - 1), mB = min(nB, NNODES - 1);

    ull accA = 0ull, accB = 0ull;
#pragma unroll 4
    for (int k = 0; k < EMBW; k += 4) {
        float4 xA = __ldg((const float4*)&emb[mA * EMBW + k]);
        float4 xB = __ldg((const float4*)&emb[mB * EMBW + k]);
        ull w0 = *(const ull*)&Ws[(k + 0) * NCLS + cp * 2];
        ull w1 = *(const ull*)&Ws[(k + 1) * NCLS + cp * 2];
        ull w2 = *(const ull*)&Ws[(k + 2) * NCLS + cp * 2];
        ull w3 = *(const ull*)&Ws[(k + 3) * NCLS + cp * 2];
        FMA_F32X2(accA, pack2(xA.x), w0);
        FMA_F32X2(accA, pack2(xA.y), w1);
        FMA_F32X2(accA, pack2(xA.z), w2);
        FMA_F32X2(accA, pack2(xA.w), w3);
        FMA_F32X2(accB, pack2(xB.x), w0);
        FMA_F32X2(accB, pack2(xB.y), w1);
        FMA_F32X2(accB, pack2(xB.z), w2);
        FMA_F32X2(accB, pack2(xB.w), w3);
    }
    if (nA < NNODES) *(ull*)&out[nA * NCLS + cp * 2] = accA;
    if (nB < NNODES) *(ull*)&out[nB * NCLS + cp * 2] = accB;
}

// ---------------- host launch ----------------------------------------------
extern "C" void kernel_launch(void* const* d_in, const int* in_sizes, int n_in,
                              void* d_out, int out_size)
{
    const float* x    = (const float*)d_in[0];
    const int*   src  = (const int*)  d_in[1];
    const int*   dst  = (const int*)  d_in[2];
    const float* W[3]  = { (const float*)d_in[3], (const float*)d_in[6], (const float*)d_in[9]  };
    const float* al[3] = { (const float*)d_in[4], (const float*)d_in[7], (const float*)d_in[10] };
    const float* ar[3] = { (const float*)d_in[5], (const float*)d_in[8], (const float*)d_in[11] };
    const float* Wproj = (const float*)d_in[12];
    float* out = (float*)d_out;

    float *el, *er, *emb;
    __half2* feath;
    int *deg, *off, *cursor, *bsum, *csrc;
    cudaGetSymbolAddress((void**)&feath,  g_feath);
    cudaGetSymbolAddress((void**)&el,     g_el);
    cudaGetSymbolAddress((void**)&er,     g_er);
    cudaGetSymbolAddress((void**)&emb,    g_emb);
    cudaGetSymbolAddress((void**)&deg,    g_deg);
    cudaGetSymbolAddress((void**)&off,    g_off);
    cudaGetSymbolAddress((void**)&cursor, g_cursor);
    cudaGetSymbolAddress((void**)&bsum,   g_bsum);
    cudaGetSymbolAddress((void**)&csrc,   g_csrc);

    const int edge_blocks = (NEDGES + 255) / 256;
    const int gemm_blocks = ((NNODES + 127) / 128) * 2;   // 2 col-blocks per row-block
    const int aggr_blocks = (NNODES * 32 + 255) / 256;

    // CSR build interleaved with layer-0 GEMM (GEMM is CSR-independent);
    // GEMM sits at launch position 4 so the profiler samples it.
    zero_deg_kernel<<<NB, 256>>>(deg);
    hist_kernel<<<edge_blocks, 256>>>(dst, deg);
    scan_block_kernel<<<NB, 256>>>(deg, off, bsum);
    gemm128_kernel<<<gemm_blocks, 256>>>(x, 128, W[0], al[0], ar[0],
                                         feath, el, er, NNODES);
    scan_bsum_kernel<<<1, 256>>>(bsum);
    add_off_kernel<<<NB, 256>>>(off, bsum, cursor);
    scatter_kernel<<<edge_blocks, 256>>>(dst, src, cursor, csrc);

    gat_aggregate_kernel<<<aggr_blocks, 256>>>(feath, el, er,
                                               off, deg, csrc, emb, 0);
    for (int l = 1; l < 3; l++) {
        gemm128_kernel<<<gemm_blocks, 256>>>(emb + (l - 1) * HD, EMBW, W[l],
                                             al[l], ar[l], feath, el, er, NNODES);
        gat_aggregate_kernel<<<aggr_blocks, 256>>>(feath, el, er,
                                                   off, deg, csrc, emb, l * HD);
    }

    proj_kernel<<<(NNODES + 31) / 32, 256>>>(emb, Wproj, out);
}

// round 13
// speedup vs baseline: 1.3314x; 1.2230x over previous
#include <cuda_runtime.h>
#include <cuda_fp16.h>
#include <cuda_bf16.h>
#include <math.h>

#define NNODES 50000
#define NEDGES 800000
#define HEADS  4
#define HD     128      // H*D
#define HD2    64       // HD/2 half2 per row
#define EMBW   384      // L*H*D
#define NCLS   32
#define NB     ((NNODES + 255) / 256)   // 196 scan blocks
#define XSTR   40                       // X smem row stride (halves), conflict-free
#define WSTR   136                      // W smem row stride (halves), conflict-free

typedef unsigned long long ull;

// packed f32x2 FMA (proj kernel)
#define FMA_F32X2(a, x, w) \
    asm("fma.rn.f32x2 %0, %1, %2, %0;" : "+l"(a) : "l"(x), "l"(w))

__device__ __forceinline__ ull pack2(float v) {
    ull r;
    asm("mov.b64 %0, {%1, %1};" : "=l"(r) : "f"(v));
    return r;
}

__device__ __forceinline__ unsigned s2u(const void* p) {
    unsigned a;
    asm("{ .reg .u64 t; cvta.to.shared.u64 t, %1; cvt.u32.u64 %0, t; }"
        : "=r"(a) : "l"(p));
    return a;
}

#define LDSM4(r, addr) \
    asm volatile("ldmatrix.sync.aligned.m8n8.x4.shared.b16 {%0,%1,%2,%3}, [%4];" \
        : "=r"((r)[0]), "=r"((r)[1]), "=r"((r)[2]), "=r"((r)[3]) : "r"(addr))
#define LDSM4T(r, addr) \
    asm volatile("ldmatrix.sync.aligned.m8n8.x4.trans.shared.b16 {%0,%1,%2,%3}, [%4];" \
        : "=r"((r)[0]), "=r"((r)[1]), "=r"((r)[2]), "=r"((r)[3]) : "r"(addr))
#define MMA16816(d, a, b0, b1) \
    asm volatile("mma.sync.aligned.m16n8k16.row.col.f32.f16.f16.f32 " \
        "{%0,%1,%2,%3}, {%4,%5,%6,%7}, {%8,%9}, {%0,%1,%2,%3};" \
        : "+f"((d)[0]), "+f"((d)[1]), "+f"((d)[2]), "+f"((d)[3]) \
        : "r"((a)[0]), "r"((a)[1]), "r"((a)[2]), "r"((a)[3]), "r"(b0), "r"(b1))

// convert 8 fp32 -> 8 fp16 hi + 8 fp16 lo (split), packed for 16B stores
__device__ __forceinline__ void cvt8(float4 va, float4 vb, uint4* uh, uint4* ul) {
    float f[8] = { va.x, va.y, va.z, va.w, vb.x, vb.y, vb.z, vb.w };
    __half2 h[4], l[4];
#pragma unroll
    for (int j = 0; j < 4; j++) {
        __half h0 = __float2half_rn(f[2*j]);
        __half h1 = __float2half_rn(f[2*j+1]);
        h[j] = __halves2half2(h0, h1);
        l[j] = __halves2half2(__float2half_rn(f[2*j]   - __half2float(h0)),
                              __float2half_rn(f[2*j+1] - __half2float(h1)));
    }
    *uh = *(uint4*)h;
    *ul = *(uint4*)l;
}

// ---------------- scratch (device globals; no allocation allowed) ----------
__device__ __half2 g_feath[NNODES * HD2];   // transformed features, fp16
__device__ float g_el[NNODES * HEADS];
__device__ float g_er[NNODES * HEADS];
__device__ float g_emb[NNODES * EMBW];
__device__ int g_deg[NNODES];
__device__ int g_off[NNODES];
__device__ int g_cursor[NNODES];
__device__ int g_bsum[NB];
__device__ int g_csrc[NEDGES];              // src node ids, grouped by dst

// ---------------- CSR build kernels -----------------------------------------

__global__ void zero_deg_kernel(int* deg) {
    int i = blockIdx.x * blockDim.x + threadIdx.x;
    if (i < NNODES) deg[i] = 0;
}

__global__ void hist_kernel(const int* __restrict__ dst, int* __restrict__ deg) {
    int e = blockIdx.x * blockDim.x + threadIdx.x;
    if (e < NEDGES) atomicAdd(&deg[dst[e]], 1);
}

__global__ void scan_block_kernel(const int* __restrict__ deg,
                                  int* __restrict__ off, int* __restrict__ bsum) {
    __shared__ int sh[256];
    int i = blockIdx.x * 256 + threadIdx.x;
    int v = (i < NNODES) ? deg[i] : 0;
    sh[threadIdx.x] = v;
    __syncthreads();
    for (int o = 1; o < 256; o <<= 1) {
        int t = (threadIdx.x >= o) ? sh[threadIdx.x - o] : 0;
        __syncthreads();
        sh[threadIdx.x] += t;
        __syncthreads();
    }
    if (i < NNODES) off[i] = sh[threadIdx.x] - v;   // exclusive
    if (threadIdx.x == 255) bsum[blockIdx.x] = sh[255];
}

__global__ void scan_bsum_kernel(int* __restrict__ bsum) {
    __shared__ int sh[256];
    int v = (threadIdx.x < NB) ? bsum[threadIdx.x] : 0;
    sh[threadIdx.x] = v;
    __syncthreads();
    for (int o = 1; o < 256; o <<= 1) {
        int t = (threadIdx.x >= o) ? sh[threadIdx.x - o] : 0;
        __syncthreads();
        sh[threadIdx.x] += t;
        __syncthreads();
    }
    if (threadIdx.x < NB) bsum[threadIdx.x] = sh[threadIdx.x] - v;
}

__global__ void add_off_kernel(int* __restrict__ off, const int* __restrict__ bsum,
                               int* __restrict__ cursor) {
    int i = blockIdx.x * 256 + threadIdx.x;
    if (i < NNODES) {
        int o = off[i] + bsum[blockIdx.x];
        off[i] = o;
        cursor[i] = o;
    }
}

__global__ void scatter_kernel(const int* __restrict__ dst, const int* __restrict__ src,
                               int* __restrict__ cursor, int* __restrict__ csrc) {
    int e = blockIdx.x * blockDim.x + threadIdx.x;
    if (e < NEDGES) {
        int p = atomicAdd(&cursor[dst[e]], 1);
        csrc[p] = src[e];
    }
}

// ---------------- compute kernels -------------------------------------------

// feat[N,128] = in[N,128] @ W[128,128] via tensor cores (mma.sync m16n8k16),
// split-fp16 (hi+lo) for ~fp32 accuracy: C = Xh*Wh + Xh*Wl + Xl*Wh, fp32 acc.
// Block: 128x128 tile, 8 warps (warp = 32 rows x 64 cols = 2x8 mma tiles).
// K chunked at 32 with in-kernel fp32->(hi,lo) smem conversion.
// Fused epilogue: el/er via smem per-(row,head) partials; feat stored fp16.
__global__ __launch_bounds__(256) void gemm128_kernel(
    const float* __restrict__ in, int in_stride,
    const float* __restrict__ W,
    const float* __restrict__ al, const float* __restrict__ ar,
    __half2* __restrict__ feath,
    float* __restrict__ el, float* __restrict__ er,
    int nrows)
{
    __shared__ __half XhS[128 * XSTR], XlS[128 * XSTR];   // 2 x 10.0 KB
    __shared__ __half WhS[32 * WSTR],  WlS[32 * WSTR];    // 2 x 8.5 KB
    __shared__ float sh_el[128][4], sh_er[128][4];        // 4 KB

    const int t    = threadIdx.x;
    const int lane = t & 31;
    const int wid  = t >> 5;
    const int wm   = wid & 3;          // warp row group (32 rows)
    const int wn   = wid >> 2;         // warp col group (64 cols)
    const int row0 = blockIdx.x * 128;

    float acc[2][8][4] = {};

    // loader indices
    const int xr = t >> 1, xc = (t & 1) * 16;   // X: 2 thr/row, 16 floats each
    const int wr = t >> 3, wc = (t & 7) * 16;   // W: 8 thr/row, 16 floats each

    for (int ch = 0; ch < 4; ch++) {
        const int kk = ch * 32;
        __syncthreads();
        // ---- load + split-convert X chunk [128][32] ----
        {
            int gr = row0 + xr;
            float4 v0, v1, v2, v3;
            if (gr < nrows) {
                const float* p = in + (size_t)gr * in_stride + kk + xc;
                v0 = *(const float4*)(p);
                v1 = *(const float4*)(p + 4);
                v2 = *(const float4*)(p + 8);
                v3 = *(const float4*)(p + 12);
            } else {
                v0 = v1 = v2 = v3 = make_float4(0.f, 0.f, 0.f, 0.f);
            }
            uint4 uh0, ul0, uh1, ul1;
            cvt8(v0, v1, &uh0, &ul0);
            cvt8(v2, v3, &uh1, &ul1);
            *(uint4*)&XhS[xr * XSTR + xc]     = uh0;
            *(uint4*)&XhS[xr * XSTR + xc + 8] = uh1;
            *(uint4*)&XlS[xr * XSTR + xc]     = ul0;
            *(uint4*)&XlS[xr * XSTR + xc + 8] = ul1;
        }
        // ---- load + split-convert W chunk [32][128] ----
        {
            const float* p = W + (size_t)(kk + wr) * 128 + wc;
            float4 v0 = *(const float4*)(p);
            float4 v1 = *(const float4*)(p + 4);
            float4 v2 = *(const float4*)(p + 8);
            float4 v3 = *(const float4*)(p + 12);
            uint4 uh0, ul0, uh1, ul1;
            cvt8(v0, v1, &uh0, &ul0);
            cvt8(v2, v3, &uh1, &ul1);
            *(uint4*)&WhS[wr * WSTR + wc]     = uh0;
            *(uint4*)&WhS[wr * WSTR + wc + 8] = uh1;
            *(uint4*)&WlS[wr * WSTR + wc]     = ul0;
            *(uint4*)&WlS[wr * WSTR + wc + 8] = ul1;
        }
        __syncthreads();

        // ---- MMA: 2 k-steps of 16 ----
#pragma unroll
        for (int ks = 0; ks < 32; ks += 16) {
            unsigned ah[2][4], alr[2][4];
#pragma unroll
            for (int mt = 0; mt < 2; mt++) {
                int arow = wm * 32 + mt * 16 + (lane & 15);
                int acol = ks + (lane >> 4) * 8;
                LDSM4(ah[mt],  s2u(&XhS[arow * XSTR + acol]));
                LDSM4(alr[mt], s2u(&XlS[arow * XSTR + acol]));
            }
#pragma unroll
            for (int np = 0; np < 4; np++) {
                int brow = ks + (lane & 15);
                int bcol = wn * 64 + np * 16 + (lane >> 4) * 8;
                unsigned bh[4], bl[4];
                LDSM4T(bh, s2u(&WhS[brow * WSTR + bcol]));
                LDSM4T(bl, s2u(&WlS[brow * WSTR + bcol]));
#pragma unroll
                for (int mt = 0; mt < 2; mt++) {
                    MMA16816(acc[mt][np*2],   ah[mt],  bh[0], bh[1]);
                    MMA16816(acc[mt][np*2+1], ah[mt],  bh[2], bh[3]);
                    MMA16816(acc[mt][np*2],   ah[mt],  bl[0], bl[1]);
                    MMA16816(acc[mt][np*2+1], ah[mt],  bl[2], bl[3]);
                    MMA16816(acc[mt][np*2],   alr[mt], bh[0], bh[1]);
                    MMA16816(acc[mt][np*2+1], alr[mt], bh[2], bh[3]);
                }
            }
        }
    }

    // ---- epilogue ----
    const int g  = lane >> 2;   // row within 8-row group
    const int tq = lane & 3;    // col quad

    float2 alv[8], arv[8];
#pragma unroll
    for (int nt = 0; nt < 8; nt++) {
        int col = wn * 64 + nt * 8 + tq * 2;
        alv[nt] = *(const float2*)&al[col];
        arv[nt] = *(const float2*)&ar[col];
    }

    // per-thread partial el/er: [mt][rowhalf][head-of-2]
    float pl[2][2][2] = {}, pr[2][2][2] = {};
#pragma unroll
    for (int mt = 0; mt < 2; mt++)
#pragma unroll
        for (int nt = 0; nt < 8; nt++) {
            int h = nt >> 2;
            pl[mt][0][h] += acc[mt][nt][0] * alv[nt].x + acc[mt][nt][1] * alv[nt].y;
            pl[mt][1][h] += acc[mt][nt][2] * alv[nt].x + acc[mt][nt][3] * alv[nt].y;
            pr[mt][0][h] += acc[mt][nt][0] * arv[nt].x + acc[mt][nt][1] * arv[nt].y;
            pr[mt][1][h] += acc[mt][nt][2] * arv[nt].x + acc[mt][nt][3] * arv[nt].y;
        }
    // reduce over the 4-lane quad
    float* fl = &pl[0][0][0];
    float* fr = &pr[0][0][0];
#pragma unroll
    for (int i = 0; i < 8; i++) {
        fl[i] += __shfl_xor_sync(0xFFFFFFFFu, fl[i], 1);
        fl[i] += __shfl_xor_sync(0xFFFFFFFFu, fl[i], 2);
        fr[i] += __shfl_xor_sync(0xFFFFFFFFu, fr[i], 1);
        fr[i] += __shfl_xor_sync(0xFFFFFFFFu, fr[i], 2);
    }
    if (tq == 0) {
#pragma unroll
        for (int mt = 0; mt < 2; mt++)
#pragma unroll
            for (int rh = 0; rh < 2; rh++) {
                int row = wm * 32 + mt * 16 + rh * 8 + g;
                sh_el[row][wn * 2 + 0] = pl[mt][rh][0];
                sh_el[row][wn * 2 + 1] = pl[mt][rh][1];
                sh_er[row][wn * 2 + 0] = pr[mt][rh][0];
                sh_er[row][wn * 2 + 1] = pr[mt][rh][1];
            }
    }

    // feat fp16 stores
#pragma unroll
    for (int mt = 0; mt < 2; mt++) {
        int gr0 = row0 + wm * 32 + mt * 16 + g;
        int gr1 = gr0 + 8;
#pragma unroll
        for (int nt = 0; nt < 8; nt++) {
            int c2 = (wn * 64 + nt * 8 + tq * 2) >> 1;
            if (gr0 < nrows)
                feath[gr0 * HD2 + c2] = __floats2half2_rn(acc[mt][nt][0], acc[mt][nt][1]);
            if (gr1 < nrows)
                feath[gr1 * HD2 + c2] = __floats2half2_rn(acc[mt][nt][2], acc[mt][nt][3]);
        }
    }

    __syncthreads();
    if (t < 128) {
        int gr = row0 + t;
        if (gr < nrows) {
            *(float4*)&el[gr * 4] =
                make_float4(sh_el[t][0], sh_el[t][1], sh_el[t][2], sh_el[t][3]);
            *(float4*)&er[gr * 4] =
                make_float4(sh_er[t][0], sh_er[t][1], sh_er[t][2], sh_er[t][3]);
        }
    }
}

// Fused per-destination softmax + aggregation + ELU + store. Warp per node.
// Lane owns features [lane*4, lane*4+4) (2 half2); head = lane>>3. Unroll x4.
__global__ __launch_bounds__(256) void gat_aggregate_kernel(
    const __half2* __restrict__ feath,
    const float* __restrict__ el, const float* __restrict__ er,
    const int* __restrict__ off, const int* __restrict__ deg,
    const int* __restrict__ csrc,
    float* __restrict__ emb, int col0)
{
    int warp = (blockIdx.x * blockDim.x + threadIdx.x) >> 5;
    if (warp >= NNODES) return;
    const int lane = threadIdx.x & 31;
    const int n    = warp;
    const int base = off[n];
    const int dg   = deg[n];

    const int h    = lane >> 3;
    const int f2   = lane * 2;          // half2 column index
    const float erh = er[n * 4 + h];

    float a0 = 0.f, a1 = 0.f, a2 = 0.f, a3 = 0.f, ssum = 0.f;
    int i = 0;
    for (; i + 4 <= dg; i += 4) {
        int s0 = csrc[base + i + 0];
        int s1 = csrc[base + i + 1];
        int s2 = csrc[base + i + 2];
        int s3 = csrc[base + i + 3];
        float x0 = el[s0 * 4 + h], x1 = el[s1 * 4 + h];
        float x2 = el[s2 * 4 + h], x3 = el[s3 * 4 + h];
        uint2 u0 = *(const uint2*)&feath[s0 * HD2 + f2];
        uint2 u1 = *(const uint2*)&feath[s1 * HD2 + f2];
        uint2 u2 = *(const uint2*)&feath[s2 * HD2 + f2];
        uint2 u3 = *(const uint2*)&feath[s3 * HD2 + f2];
        x0 += erh; x0 = (x0 > 0.f) ? x0 : 0.2f * x0; float e0 = __expf(x0);
        x1 += erh; x1 = (x1 > 0.f) ? x1 : 0.2f * x1; float e1 = __expf(x1);
        x2 += erh; x2 = (x2 > 0.f) ? x2 : 0.2f * x2; float e2 = __expf(x2);
        x3 += erh; x3 = (x3 > 0.f) ? x3 : 0.2f * x3; float e3 = __expf(x3);
        ssum += (e0 + e1) + (e2 + e3);
        float2 fa, fb;
        fa = __half22float2(*(__half2*)&u0.x); fb = __half22float2(*(__half2*)&u0.y);
        a0 = fmaf(e0, fa.x, a0); a1 = fmaf(e0, fa.y, a1);
        a2 = fmaf(e0, fb.x, a2); a3 = fmaf(e0, fb.y, a3);
        fa = __half22float2(*(__half2*)&u1.x); fb = __half22float2(*(__half2*)&u1.y);
        a0 = fmaf(e1, fa.x, a0); a1 = fmaf(e1, fa.y, a1);
        a2 = fmaf(e1, fb.x, a2); a3 = fmaf(e1, fb.y, a3);
        fa = __half22float2(*(__half2*)&u2.x); fb = __half22float2(*(__half2*)&u2.y);
        a0 = fmaf(e2, fa.x, a0); a1 = fmaf(e2, fa.y, a1);
        a2 = fmaf(e2, fb.x, a2); a3 = fmaf(e2, fb.y, a3);
        fa = __half22float2(*(__half2*)&u3.x); fb = __half22float2(*(__half2*)&u3.y);
        a0 = fmaf(e3, fa.x, a0); a1 = fmaf(e3, fa.y, a1);
        a2 = fmaf(e3, fb.x, a2); a3 = fmaf(e3, fb.y, a3);
    }
    for (; i < dg; i++) {
        int s = csrc[base + i];
        float x = el[s * 4 + h] + erh;
        x = (x > 0.f) ? x : 0.2f * x;
        float ex = __expf(x);
        ssum += ex;
        uint2 u = *(const uint2*)&feath[s * HD2 + f2];
        float2 fa = __half22float2(*(__half2*)&u.x);
        float2 fb = __half22float2(*(__half2*)&u.y);
        a0 = fmaf(ex, fa.x, a0); a1 = fmaf(ex, fa.y, a1);
        a2 = fmaf(ex, fb.x, a2); a3 = fmaf(ex, fb.y, a3);
    }
    float inv = (ssum != 0.f) ? (1.0f / ssum) : 0.0f;
    a0 *= inv; a1 *= inv; a2 *= inv; a3 *= inv;
    a0 = (a0 > 0.f) ? a0 : expm1f(a0);
    a1 = (a1 > 0.f) ? a1 : expm1f(a1);
    a2 = (a2 > 0.f) ? a2 : expm1f(a2);
    a3 = (a3 > 0.f) ? a3 : expm1f(a3);
    *(float4*)&emb[n * EMBW + col0 + lane * 4] = make_float4(a0, a1, a2, a3);
}

// logits = emb @ Wproj via f32x2. Block: 32 nodes x 32 classes.
// thread t = (nl:16, cp:16): nodes nb+nl, nb+nl+16; classes 2cp, 2cp+1.
__global__ __launch_bounds__(256) void proj_kernel(
    const float* __restrict__ emb,
    const float* __restrict__ Wp,
    float* __restrict__ out)
{
    __shared__ float Ws[EMBW * NCLS];   // 48 KB, k-major (class pairs contiguous)
    int t = threadIdx.x;
    for (int i = t; i < EMBW * NCLS; i += 256) Ws[i] = Wp[i];
    __syncthreads();

    const int cp = t & 15;
    const int nl = t >> 4;
    const int nb = blockIdx.x * 32;
    int nA = nb + nl;
    int nB = nb + nl + 16;
    int mA = min(nA, NNODES - 1), mB = min(nB, NNODES - 1);

    ull accA = 0ull, accB = 0ull;
#pragma unroll 4
    for (int k = 0; k < EMBW; k += 4) {
        float4 xA = __ldg((const float4*)&emb[mA * EMBW + k]);
        float4 xB = __ldg((const float4*)&emb[mB * EMBW + k]);
        ull w0 = *(const ull*)&Ws[(k + 0) * NCLS + cp * 2];
        ull w1 = *(const ull*)&Ws[(k + 1) * NCLS + cp * 2];
        ull w2 = *(const ull*)&Ws[(k + 2) * NCLS + cp * 2];
        ull w3 = *(const ull*)&Ws[(k + 3) * NCLS + cp * 2];
        FMA_F32X2(accA, pack2(xA.x), w0);
        FMA_F32X2(accA, pack2(xA.y), w1);
        FMA_F32X2(accA, pack2(xA.z), w2);
        FMA_F32X2(accA, pack2(xA.w), w3);
        FMA_F32X2(accB, pack2(xB.x), w0);
        FMA_F32X2(accB, pack2(xB.y), w1);
        FMA_F32X2(accB, pack2(xB.z), w2);
        FMA_F32X2(accB, pack2(xB.w), w3);
    }
    if (nA < NNODES) *(ull*)&out[nA * NCLS + cp * 2] = accA;
    if (nB < NNODES) *(ull*)&out[nB * NCLS + cp * 2] = accB;
}

// ---------------- host launch ----------------------------------------------
extern "C" void kernel_launch(void* const* d_in, const int* in_sizes, int n_in,
                              void* d_out, int out_size)
{
    const float* x    = (const float*)d_in[0];
    const int*   src  = (const int*)  d_in[1];
    const int*   dst  = (const int*)  d_in[2];
    const float* W[3]  = { (const float*)d_in[3], (const float*)d_in[6], (const float*)d_in[9]  };
    const float* al[3] = { (const float*)d_in[4], (const float*)d_in[7], (const float*)d_in[10] };
    const float* ar[3] = { (const float*)d_in[5], (const float*)d_in[8], (const float*)d_in[11] };
    const float* Wproj = (const float*)d_in[12];
    float* out = (float*)d_out;

    float *el, *er, *emb;
    __half2* feath;
    int *deg, *off, *cursor, *bsum, *csrc;
    cudaGetSymbolAddress((void**)&feath,  g_feath);
    cudaGetSymbolAddress((void**)&el,     g_el);
    cudaGetSymbolAddress((void**)&er,     g_er);
    cudaGetSymbolAddress((void**)&emb,    g_emb);
    cudaGetSymbolAddress((void**)&deg,    g_deg);
    cudaGetSymbolAddress((void**)&off,    g_off);
    cudaGetSymbolAddress((void**)&cursor, g_cursor);
    cudaGetSymbolAddress((void**)&bsum,   g_bsum);
    cudaGetSymbolAddress((void**)&csrc,   g_csrc);

    const int edge_blocks = (NEDGES + 255) / 256;
    const int gemm_blocks = (NNODES + 127) / 128;
    const int aggr_blocks = (NNODES * 32 + 255) / 256;

    // CSR build interleaved with layer-0 GEMM (GEMM is CSR-independent);
    // GEMM sits at launch position 4 so the profiler samples it.
    zero_deg_kernel<<<NB, 256>>>(deg);
    hist_kernel<<<edge_blocks, 256>>>(dst, deg);
    scan_block_kernel<<<NB, 256>>>(deg, off, bsum);
    gemm128_kernel<<<gemm_blocks, 256>>>(x, 128, W[0], al[0], ar[0],
                                         feath, el, er, NNODES);
    scan_bsum_kernel<<<1, 256>>>(bsum);
    add_off_kernel<<<NB, 256>>>(off, bsum, cursor);
    scatter_kernel<<<edge_blocks, 256>>>(dst, src, cursor, csrc);

    gat_aggregate_kernel<<<aggr_blocks, 256>>>(feath, el, er,
                                               off, deg, csrc, emb, 0);
    for (int l = 1; l < 3; l++) {
        gemm128_kernel<<<gemm_blocks, 256>>>(emb + (l - 1) * HD, EMBW, W[l],
                                             al[l], ar[l], feath, el, er, NNODES);
        gat_aggregate_kernel<<<aggr_blocks, 256>>>(feath, el, er,
                                                   off, deg, csrc, emb, l * HD);
    }

    proj_kernel<<<(NNODES + 31) / 32, 256>>>(emb, Wproj, out);
}